// round 10
// baseline (speedup 1.0000x reference)
#include <cuda_runtime.h>
#include <cstdint>

#define NB 8      // batch
#define NP 3249   // grid points
#define NS 128    // axon segments
#define NE 60     // electrodes
#define NWARPS 7
#define THREADS (NWARPS * 32)            // 224
#define NBLOCKS 148
#define HALF_FLOATS (64 * NE)            // 3840 floats = 15360 B (segments 0-63 / 64-127)
#define HALF_BYTES (HALF_FLOATS * 4)
#define TILE_FLOATS (NS * NE)            // 7680

#define SMEM_BYTES (NWARPS * 2 * HALF_BYTES + NE * NB * 4 + NWARPS * 2 * 8 + 64)

__device__ __forceinline__ unsigned long long dup2(float x) {
    unsigned long long r;
    asm("mov.b64 %0, {%1, %1};" : "=l"(r) : "f"(x));
    return r;
}
__device__ __forceinline__ void fma2(unsigned long long& d,
                                     unsigned long long a,
                                     unsigned long long b) {
    asm("fma.rn.f32x2 %0, %1, %2, %0;" : "+l"(d) : "l"(a), "l"(b));
}

__device__ __forceinline__ void mbar_wait(uint32_t addr, uint32_t parity) {
    uint32_t done;
    asm volatile("{\n\t.reg .pred p;\n\t"
                 "mbarrier.try_wait.parity.acquire.cta.shared::cta.b64 p, [%1], %2;\n\t"
                 "selp.b32 %0, 1, 0, p;\n\t}"
                 : "=r"(done) : "r"(addr), "r"(parity) : "memory");
    while (!done) {
        asm volatile("{\n\t.reg .pred p;\n\t"
                     "mbarrier.try_wait.parity.acquire.cta.shared::cta.b64 p, [%1], %2, 0x989680;\n\t"
                     "selp.b32 %0, 1, 0, p;\n\t}"
                     : "=r"(done) : "r"(addr), "r"(parity) : "memory");
    }
}

__device__ __forceinline__ void tma_fill(uint32_t dst, uint32_t mbar_addr,
                                         const float* src) {
    asm volatile("mbarrier.arrive.expect_tx.shared.b64 _, [%0], %1;"
                 :: "r"(mbar_addr), "r"((uint32_t)HALF_BYTES) : "memory");
    asm volatile("cp.async.bulk.shared::cluster.global.mbarrier::complete_tx::bytes "
                 "[%0], [%1], %2, [%3];"
                 :: "r"(dst), "l"(src), "r"((uint32_t)HALF_BYTES), "r"(mbar_addr)
                 : "memory");
}

// Persistent: 148 blocks x 224 threads (7 warps). Each warp owns TWO private
// half-tile stages (segments 0-63 and 64-127 of its current point), each with
// its own mbarrier — waiter == refiller per stage, parity flips once per
// point, so the proven race-free invariant holds, but now the warp computes
// half h while half h^1 (and, after refill, the next point's half h) is in
// flight: the TMA latency that was exposed at depth-1 is hidden by compute.
__global__ __launch_bounds__(THREADS, 1)
void axon_map_kernel(const float* __restrict__ amp,
                     const float* __restrict__ pexp,
                     float* __restrict__ out) {
    extern __shared__ __align__(128) char smem_raw[];
    float* tiles = reinterpret_cast<float*>(smem_raw);              // [NWARPS][2][3840]
    float* ampt  = tiles + NWARPS * 2 * HALF_FLOATS;                // [NE][NB]
    unsigned long long* mbar =
        reinterpret_cast<unsigned long long*>(ampt + NE * NB);      // [NWARPS][2]

    const int tid  = threadIdx.x;
    const int warp = tid >> 5;
    const int lane = tid & 31;
    const int bid  = blockIdx.x;

    const float* half0 = tiles + (warp * 2 + 0) * HALF_FLOATS;
    const float* half1 = tiles + (warp * 2 + 1) * HALF_FLOATS;
    const uint32_t h0_addr = (uint32_t)__cvta_generic_to_shared(half0);
    const uint32_t h1_addr = (uint32_t)__cvta_generic_to_shared(half1);
    const uint32_t m0_addr = (uint32_t)__cvta_generic_to_shared(&mbar[warp * 2 + 0]);
    const uint32_t m1_addr = (uint32_t)__cvta_generic_to_shared(&mbar[warp * 2 + 1]);

    if (tid < NWARPS * 2) {
        const uint32_t a = (uint32_t)__cvta_generic_to_shared(&mbar[tid]);
        asm volatile("mbarrier.init.shared.b64 [%0], 1;" :: "r"(a) : "memory");
    }
    for (int i = tid; i < NB * NE; i += THREADS) {
        const int b = i / NE, e = i % NE;
        ampt[e * NB + b] = amp[i];
    }
    __syncthreads();

    // Prologue: fill both halves of this warp's first point.
    const int p0 = bid + NBLOCKS * warp;   // <= 1035 < NP always
    if (lane == 0) {
        tma_fill(h0_addr, m0_addr, pexp + (size_t)p0 * TILE_FLOATS);
        tma_fill(h1_addr, m1_addr, pexp + (size_t)p0 * TILE_FLOATS + HALF_FLOATS);
    }

    uint32_t parity = 0;
    for (int p = p0; p < NP; p += NBLOCKS * NWARPS) {
        const int pn = p + NBLOCKS * NWARPS;
        const float* src_n = pexp + (size_t)pn * TILE_FLOATS;

        unsigned long long acc[4][4];   // [row r][batch pair q]; r 0-1 half0, 2-3 half1
        #pragma unroll
        for (int r = 0; r < 4; r++)
            #pragma unroll
            for (int q = 0; q < 4; q++) acc[r][q] = 0ull;

        #pragma unroll
        for (int h = 0; h < 2; h++) {
            mbar_wait(h ? m1_addr : m0_addr, parity);
            const float* half = h ? half1 : half0;
            const float* rowA = half + lane * NE;          // local rows: lane, lane+32
            const float* rowB = half + (lane + 32) * NE;
            unsigned long long* aA = acc[2 * h + 0];
            unsigned long long* aB = acc[2 * h + 1];

            #pragma unroll
            for (int j = 0; j < NE / 4; j++) {
                const float4 pA = *reinterpret_cast<const float4*>(rowA + 4 * j);
                const float4 pB = *reinterpret_cast<const float4*>(rowB + 4 * j);
                const float eA[4] = {pA.x, pA.y, pA.z, pA.w};
                const float eB[4] = {pB.x, pB.y, pB.z, pB.w};
                #pragma unroll
                for (int k = 0; k < 4; k++) {
                    const int e = 4 * j + k;
                    const ulonglong2 alo = *reinterpret_cast<const ulonglong2*>(ampt + e * NB);
                    const ulonglong2 ahi = *reinterpret_cast<const ulonglong2*>(ampt + e * NB + 4);
                    const unsigned long long dA = dup2(eA[k]);
                    fma2(aA[0], dA, alo.x);
                    fma2(aA[1], dA, alo.y);
                    fma2(aA[2], dA, ahi.x);
                    fma2(aA[3], dA, ahi.y);
                    const unsigned long long dB = dup2(eB[k]);
                    fma2(aB[0], dB, alo.x);
                    fma2(aB[1], dB, alo.y);
                    fma2(aB[2], dB, ahi.x);
                    fma2(aB[3], dB, ahi.y);
                }
            }

            // This half consumed -> refill it with the NEXT point's same half.
            // Fence orders our generic-proxy LDS reads before the async-proxy
            // TMA write; the fill overlaps the other half's compute + argmax.
            if (pn < NP) {
                asm volatile("fence.proxy.async.shared::cta;" ::: "memory");
                __syncwarp();
                if (lane == 0)
                    tma_fill(h ? h1_addr : h0_addr, h ? m1_addr : m0_addr,
                             src_n + h * HALF_FLOATS);
            }
        }
        parity ^= 1u;

        // abs-argmax over 128 segments per batch: 4-way local, 5-step shuffle.
        #pragma unroll
        for (int b = 0; b < NB; b++) {
            const int q = b >> 1;
            float bv = 0.0f, ba = -1.0f;
            #pragma unroll
            for (int r = 0; r < 4; r++) {
                const unsigned long long pa = acc[r][q];
                const float v = __uint_as_float((b & 1) ? (uint32_t)(pa >> 32) : (uint32_t)pa);
                const float a = fabsf(v);
                if (a > ba) { ba = a; bv = v; }
            }
            #pragma unroll
            for (int off = 16; off > 0; off >>= 1) {
                const float oa = __shfl_xor_sync(0xffffffffu, ba, off);
                const float ov = __shfl_xor_sync(0xffffffffu, bv, off);
                if (oa > ba) { ba = oa; bv = ov; }
            }
            if (lane == 0) out[b * NP + p] = bv;   // threshold |v|>0 is identity
        }
    }
}

extern "C" void kernel_launch(void* const* d_in, const int* in_sizes, int n_in,
                              void* d_out, int out_size) {
    (void)n_in; (void)out_size;
    const float* a0 = (const float*)d_in[0];
    const float* a1 = (const float*)d_in[1];
    const float* amp  = a0;
    const float* pexp = a1;
    if (in_sizes[0] != NB * NE) { amp = a1; pexp = a0; }

    cudaFuncSetAttribute(axon_map_kernel,
                         cudaFuncAttributeMaxDynamicSharedMemorySize, SMEM_BYTES);
    axon_map_kernel<<<NBLOCKS, THREADS, SMEM_BYTES>>>(amp, pexp, (float*)d_out);
}

// round 11
// speedup vs baseline: 1.0884x; 1.0884x over previous
#include <cuda_runtime.h>
#include <cstdint>

#define NB 8      // batch
#define NP 3249   // grid points
#define NS 128    // axon segments
#define NE 60     // electrodes
#define NWARPS 7
#define THREADS (NWARPS * 32)          // 224
#define NBLOCKS 148
#define TILE_FLOATS (NS * NE)          // 7680
#define TILE_BYTES (TILE_FLOATS * 4)   // 30720
#define STRIDE (NBLOCKS * NWARPS)      // 1036

#define SMEM_BYTES (NWARPS * TILE_BYTES + NE * NB * 4 + NWARPS * 8 + 64)

__device__ __forceinline__ unsigned long long dup2(float x) {
    unsigned long long r;
    asm("mov.b64 %0, {%1, %1};" : "=l"(r) : "f"(x));
    return r;
}
__device__ __forceinline__ void fma2(unsigned long long& d,
                                     unsigned long long a,
                                     unsigned long long b) {
    asm("fma.rn.f32x2 %0, %1, %2, %0;" : "+l"(d) : "l"(a), "l"(b));
}

__device__ __forceinline__ void mbar_wait(uint32_t addr, uint32_t parity) {
    uint32_t done;
    asm volatile("{\n\t.reg .pred p;\n\t"
                 "mbarrier.try_wait.parity.acquire.cta.shared::cta.b64 p, [%1], %2;\n\t"
                 "selp.b32 %0, 1, 0, p;\n\t}"
                 : "=r"(done) : "r"(addr), "r"(parity) : "memory");
    while (!done) {
        asm volatile("{\n\t.reg .pred p;\n\t"
                     "mbarrier.try_wait.parity.acquire.cta.shared::cta.b64 p, [%1], %2, 0x989680;\n\t"
                     "selp.b32 %0, 1, 0, p;\n\t}"
                     : "=r"(done) : "r"(addr), "r"(parity) : "memory");
    }
}

__device__ __forceinline__ void tma_fill(uint32_t tile_addr, uint32_t mbar_addr,
                                         const float* src) {
    asm volatile("mbarrier.arrive.expect_tx.shared.b64 _, [%0], %1;"
                 :: "r"(mbar_addr), "r"((uint32_t)TILE_BYTES) : "memory");
    asm volatile("cp.async.bulk.shared::cluster.global.mbarrier::complete_tx::bytes "
                 "[%0], [%1], %2, [%3];"
                 :: "r"(tile_addr), "l"(src), "r"((uint32_t)TILE_BYTES), "r"(mbar_addr)
                 : "memory");
}

// Fire-and-forget DRAM -> L2 bulk prefetch of a whole tile.
__device__ __forceinline__ void l2_prefetch(const float* src) {
    asm volatile("cp.async.bulk.prefetch.L2.global [%0], %1;"
                 :: "l"(src), "r"((uint32_t)TILE_BYTES) : "memory");
}

// Persistent: 148 blocks x 224 threads (7 warps). Each warp owns ONE private
// full tile stage + mbarrier (waiter == refiller: race-free parity), computes
// a whole point (4 rows/thread -> minimal amp broadcast traffic), argmax via
// pure warp shuffles. NEW: a cp.async.bulk.prefetch.L2 stream runs 2 points
// ahead of the fills, so the mbarrier-tracked TMA fill services from L2
// instead of DRAM -- the DRAM read has no consumer dependency and the exposed
// per-point fill latency collapses to the L2 hit path.
__global__ __launch_bounds__(THREADS, 1)
void axon_map_kernel(const float* __restrict__ amp,
                     const float* __restrict__ pexp,
                     float* __restrict__ out) {
    extern __shared__ __align__(128) char smem_raw[];
    float* tiles = reinterpret_cast<float*>(smem_raw);              // [NWARPS][7680]
    float* ampt  = tiles + NWARPS * TILE_FLOATS;                    // [NE][NB]
    unsigned long long* mbar =
        reinterpret_cast<unsigned long long*>(ampt + NE * NB);      // [NWARPS]

    const int tid  = threadIdx.x;
    const int warp = tid >> 5;
    const int lane = tid & 31;
    const int bid  = blockIdx.x;

    const uint32_t my_tile_addr =
        (uint32_t)__cvta_generic_to_shared(tiles + warp * TILE_FLOATS);
    const uint32_t my_mbar_addr =
        (uint32_t)__cvta_generic_to_shared(&mbar[warp]);

    if (tid < NWARPS) {
        const uint32_t a = (uint32_t)__cvta_generic_to_shared(&mbar[tid]);
        asm volatile("mbarrier.init.shared.b64 [%0], 1;" :: "r"(a) : "memory");
    }
    for (int i = tid; i < NB * NE; i += THREADS) {
        const int b = i / NE, e = i % NE;
        ampt[e * NB + b] = amp[i];
    }
    __syncthreads();

    const float* tile = tiles + warp * TILE_FLOATS;

    // Prologue: fill own stage for first point; prefetch the second point.
    const int p0 = bid + NBLOCKS * warp;   // <= 1035 < NP always
    if (lane == 0) {
        tma_fill(my_tile_addr, my_mbar_addr, pexp + (size_t)p0 * TILE_FLOATS);
        if (p0 + STRIDE < NP)
            l2_prefetch(pexp + (size_t)(p0 + STRIDE) * TILE_FLOATS);
    }

    uint32_t parity = 0;
    for (int p = p0; p < NP; p += STRIDE) {
        mbar_wait(my_mbar_addr, parity);
        parity ^= 1u;

        unsigned long long acc[4][4];   // [row r][batch pair q]
        #pragma unroll
        for (int r = 0; r < 4; r++)
            #pragma unroll
            for (int q = 0; q < 4; q++) acc[r][q] = 0ull;

        #pragma unroll
        for (int j = 0; j < NE / 4; j++) {
            float4 pe[4];
            #pragma unroll
            for (int r = 0; r < 4; r++)
                pe[r] = *reinterpret_cast<const float4*>(tile + (lane + 32 * r) * NE + 4 * j);
            #pragma unroll
            for (int k = 0; k < 4; k++) {
                const int e = 4 * j + k;
                const ulonglong2 alo = *reinterpret_cast<const ulonglong2*>(ampt + e * NB);
                const ulonglong2 ahi = *reinterpret_cast<const ulonglong2*>(ampt + e * NB + 4);
                #pragma unroll
                for (int r = 0; r < 4; r++) {
                    const float pv = (k == 0) ? pe[r].x : (k == 1) ? pe[r].y
                                   : (k == 2) ? pe[r].z : pe[r].w;
                    const unsigned long long d = dup2(pv);
                    fma2(acc[r][0], d, alo.x);
                    fma2(acc[r][1], d, alo.y);
                    fma2(acc[r][2], d, ahi.x);
                    fma2(acc[r][3], d, ahi.y);
                }
            }
        }

        // Refill own stage for the next point (L2-resident via the prefetch
        // issued one iteration ago) and prefetch two points ahead. Fence
        // orders our generic-proxy tile reads before the async-proxy write;
        // both async ops then overlap the argmax reduction below.
        const int pn  = p + STRIDE;
        const int pn2 = p + 2 * STRIDE;
        if (pn < NP) {
            asm volatile("fence.proxy.async.shared::cta;" ::: "memory");
            __syncwarp();
            if (lane == 0) {
                tma_fill(my_tile_addr, my_mbar_addr,
                         pexp + (size_t)pn * TILE_FLOATS);
                if (pn2 < NP)
                    l2_prefetch(pexp + (size_t)pn2 * TILE_FLOATS);
            }
        }

        // abs-argmax over 128 segments per batch: 4-way local, 5-step shuffle.
        #pragma unroll
        for (int b = 0; b < NB; b++) {
            const int q = b >> 1;
            float bv = 0.0f, ba = -1.0f;
            #pragma unroll
            for (int r = 0; r < 4; r++) {
                const unsigned long long pa = acc[r][q];
                const float v = __uint_as_float((b & 1) ? (uint32_t)(pa >> 32) : (uint32_t)pa);
                const float a = fabsf(v);
                if (a > ba) { ba = a; bv = v; }
            }
            #pragma unroll
            for (int off = 16; off > 0; off >>= 1) {
                const float oa = __shfl_xor_sync(0xffffffffu, ba, off);
                const float ov = __shfl_xor_sync(0xffffffffu, bv, off);
                if (oa > ba) { ba = oa; bv = ov; }
            }
            if (lane == 0) out[b * NP + p] = bv;   // threshold |v|>0 is identity
        }
    }
}

extern "C" void kernel_launch(void* const* d_in, const int* in_sizes, int n_in,
                              void* d_out, int out_size) {
    (void)n_in; (void)out_size;
    const float* a0 = (const float*)d_in[0];
    const float* a1 = (const float*)d_in[1];
    const float* amp  = a0;
    const float* pexp = a1;
    if (in_sizes[0] != NB * NE) { amp = a1; pexp = a0; }

    cudaFuncSetAttribute(axon_map_kernel,
                         cudaFuncAttributeMaxDynamicSharedMemorySize, SMEM_BYTES);
    axon_map_kernel<<<NBLOCKS, THREADS, SMEM_BYTES>>>(amp, pexp, (float*)d_out);
}